// round 12
// baseline (speedup 1.0000x reference)
#include <cuda_runtime.h>
#include <cuda_fp16.h>
#include <cstdint>

// Problem: P=4, B=2, S=2048, D=2048, H=16, HK=4, DH=128, G=4
#define M_ROWS 16384
#define KD     2048
#define NQKV   3072   // 2048 q | 512 k | 512 v

// -------- scratch (device globals: allocation-free) --------
__device__ __half g_hs_h[(size_t)M_ROWS * KD];
__device__ __half g_wqkv_h[(size_t)KD * NQKV];
__device__ __half g_wo_h[(size_t)2048 * 2048];
__device__ __half g_ctx_h[(size_t)M_ROWS * 2048];
__device__ float  g_qkv[(size_t)M_ROWS * NQKV];
__device__ float  g_bias[NQKV];

// -------- GEMM config: 4 warps, warp tile 64x64 (2x2 warp grid) --------
#define BM 128
#define BN 128
#define BK 32                  // halves per k-stage
#define NTILE (KD / BK)        // 64
#define STAGES 4
#define ASTR 40                // halves per A smem row (80B)
#define BSTR 136               // halves per B smem row (272B)
#define A_STAGE (BM * ASTR)    // 5120 halves
#define B_STAGE (BK * BSTR)    // 4352 halves
#define SMEM_BYTES (STAGES * (A_STAGE + B_STAGE) * 2)   // 75776

// -------- PTX helpers --------
__device__ __forceinline__ uint32_t s2u(const void* p) {
    uint32_t a;
    asm("{ .reg .u64 t; cvta.to.shared.u64 t, %1; cvt.u32.u64 %0, t; }" : "=r"(a) : "l"(p));
    return a;
}
__device__ __forceinline__ void cp16(uint32_t dst, const void* src) {
    asm volatile("cp.async.cg.shared.global [%0], [%1], 16;" :: "r"(dst), "l"(src));
}
__device__ __forceinline__ void cp_commit() {
    asm volatile("cp.async.commit_group;" ::: "memory");
}
__device__ __forceinline__ void ldsm4(uint32_t* r, uint32_t addr) {
    asm volatile("ldmatrix.sync.aligned.m8n8.x4.shared.b16 {%0,%1,%2,%3}, [%4];"
        : "=r"(r[0]), "=r"(r[1]), "=r"(r[2]), "=r"(r[3]) : "r"(addr));
}
__device__ __forceinline__ void ldsm4t(uint32_t* r, uint32_t addr) {
    asm volatile("ldmatrix.sync.aligned.m8n8.x4.trans.shared.b16 {%0,%1,%2,%3}, [%4];"
        : "=r"(r[0]), "=r"(r[1]), "=r"(r[2]), "=r"(r[3]) : "r"(addr));
}
// non-volatile — lets ptxas interleave HMMAs with later LDSMs.
__device__ __forceinline__ void mma_h(float* c, const uint32_t* a, const uint32_t* b) {
    asm("mma.sync.aligned.m16n8k16.row.col.f32.f16.f16.f32 "
        "{%0,%1,%2,%3}, {%4,%5,%6,%7}, {%8,%9}, {%0,%1,%2,%3};"
        : "+f"(c[0]), "+f"(c[1]), "+f"(c[2]), "+f"(c[3])
        : "r"(a[0]), "r"(a[1]), "r"(a[2]), "r"(a[3]), "r"(b[0]), "r"(b[1]));
}

// -------- fp16 tensor-core GEMM: C[M,N](f32) = A[M,K](f16) @ B[K,N](f16) (+bias) --------
// 4 warps, 64x64 warp tiles; warp-phase skew + mid-kk prefetch (round-11 winners kept).
__global__ void __launch_bounds__(128, 2)
gemm_h(const __half* __restrict__ A, const __half* __restrict__ B,
       const float* __restrict__ bias, float* __restrict__ C, int N)
{
    extern __shared__ __half sm[];
    __half* sA = sm;
    __half* sB = sm + STAGES * A_STAGE;

    const int t = threadIdx.x, lane = t & 31, warp = t >> 5;
    const int wm = warp >> 1, wn = warp & 1;      // 2 x 2 warp grid, warp tile 64x64
    const int g = lane >> 2, tg = lane & 3;
    const int bm = blockIdx.y * BM, bn = blockIdx.x * BN;

    // cp.async staging map (128 threads)
    const int ar = t;                   // A row 0..127; halves 0..31 (64B) per thread
    const int br = t >> 2;              // B row 0..31
    const int bc = (t & 3) * 32;        // halves 0/32/64/96 (64B each)

    const __half* Ag = A + (size_t)(bm + ar) * KD;
    const __half* Bg = B + (size_t)br * N + bn + bc;

    // ---- precomputed integer SMEM addresses (bytes) ----
    const uint32_t sAu = s2u(sA);
    const uint32_t sBu = s2u(sB);
    const uint32_t daBase = sAu + (uint32_t)(ar * ASTR) * 2;
    const uint32_t dbBase = sBu + (uint32_t)(br * BSTR + bc) * 2;
    const int a_row = (lane & 15);
    const int a_col = ((lane >> 4) << 3);
    const int b_row = (lane & 7) + (((lane >> 3) & 1) << 3);
    const int b_col = ((lane >> 4) << 3);
    const uint32_t aW = sAu + (uint32_t)((wm * 64 + a_row) * ASTR + a_col) * 2;
    const uint32_t bW = sBu + (uint32_t)(b_row * BSTR + wn * 64 + b_col) * 2;

    const int kk0 = warp & 1;           // phase skew: odd warps start at kk=1

    float acc[4][8][4];
#pragma unroll
    for (int i = 0; i < 4; i++)
#pragma unroll
        for (int j = 0; j < 8; j++)
#pragma unroll
            for (int l = 0; l < 4; l++) acc[i][j][l] = 0.f;

    // prologue: issue STAGES-1 stages
#pragma unroll
    for (int s = 0; s < STAGES - 1; s++) {
        const uint32_t da = daBase + s * (A_STAGE * 2);
        const __half* Ap = Ag + s * BK;
        cp16(da, Ap); cp16(da + 16, Ap + 8); cp16(da + 32, Ap + 16); cp16(da + 48, Ap + 24);
        const uint32_t db = dbBase + s * (B_STAGE * 2);
        const __half* Bp = Bg + (size_t)s * BK * N;
        cp16(db, Bp); cp16(db + 16, Bp + 8); cp16(db + 32, Bp + 16); cp16(db + 48, Bp + 24);
        cp_commit();
    }

    for (int kt = 0; kt < NTILE; kt++) {
        const int s = kt & (STAGES - 1);
        asm volatile("cp.async.wait_group %0;" :: "n"(STAGES - 2));
        __syncthreads();

        const uint32_t aS = aW + s * (A_STAGE * 2);
        const uint32_t bS = bW + s * (B_STAGE * 2);

#pragma unroll
        for (int pass = 0; pass < 2; pass++) {
            const int kk = kk0 ^ pass;
            const uint32_t aK = aS + kk * 32;
            const uint32_t bK = bS + kk * (16 * BSTR * 2);
            uint32_t bf[8][2];
#pragma unroll
            for (int nb = 0; nb < 4; nb++) {
                uint32_t rr[4];
                ldsm4t(rr, bK + nb * 32);
                bf[nb * 2][0] = rr[0]; bf[nb * 2][1] = rr[1];
                bf[nb * 2 + 1][0] = rr[2]; bf[nb * 2 + 1][1] = rr[3];
            }
            uint32_t af[4][4];
#pragma unroll
            for (int mt = 0; mt < 4; mt++)
                ldsm4(af[mt], aK + mt * (16 * ASTR * 2));
#pragma unroll
            for (int mt = 0; mt < 4; mt++)
#pragma unroll
                for (int nt = 0; nt < 8; nt++)
                    mma_h(acc[mt][nt], af[mt], bf[nt]);

            // prefetch issued between the two kk passes (de-phased smem writes)
            if (pass == 0 && kt + STAGES - 1 < NTILE) {
                const int sn = (kt + STAGES - 1) & (STAGES - 1);
                const uint32_t da = daBase + sn * (A_STAGE * 2);
                const __half* Ap = Ag + (kt + STAGES - 1) * BK;
                cp16(da, Ap); cp16(da + 16, Ap + 8); cp16(da + 32, Ap + 16); cp16(da + 48, Ap + 24);
                const uint32_t db = dbBase + sn * (B_STAGE * 2);
                const __half* Bp = Bg + (size_t)(kt + STAGES - 1) * BK * N;
                cp16(db, Bp); cp16(db + 16, Bp + 8); cp16(db + 32, Bp + 16); cp16(db + 48, Bp + 24);
                cp_commit();
            }
        }
    }

    // epilogue
#pragma unroll
    for (int mt = 0; mt < 4; mt++) {
        const int r0 = bm + wm * 64 + mt * 16 + g;
#pragma unroll
        for (int nt = 0; nt < 8; nt++) {
            const int c0 = bn + wn * 64 + nt * 8 + tg * 2;
            float bb0 = bias ? bias[c0] : 0.f;
            float bb1 = bias ? bias[c0 + 1] : 0.f;
            float2 v0 = make_float2(acc[mt][nt][0] + bb0, acc[mt][nt][1] + bb1);
            float2 v1 = make_float2(acc[mt][nt][2] + bb0, acc[mt][nt][3] + bb1);
            *(float2*)(C + (size_t)r0 * N + c0) = v0;
            *(float2*)(C + (size_t)(r0 + 8) * N + c0) = v1;
        }
    }
}

// -------- single fused conversion / packing kernel --------
#define N1 8388608
#define N2 1572864
#define N3 1048576
__global__ void conv_all(const float4* __restrict__ hs,
                         const float4* __restrict__ Wq, const float4* __restrict__ Wk,
                         const float4* __restrict__ Wv, const float4* __restrict__ Wo,
                         const float* __restrict__ bq, const float* __restrict__ bk,
                         const float* __restrict__ bv,
                         uint2* __restrict__ ohs, uint2* __restrict__ owqkv,
                         uint2* __restrict__ owo, float* __restrict__ obias)
{
    const int tid0 = blockIdx.x * blockDim.x + threadIdx.x;
    if (tid0 < NQKV)
        obias[tid0] = (tid0 < 2048) ? bq[tid0] : (tid0 < 2560) ? bk[tid0 - 2048] : bv[tid0 - 2560];

    const int stride = gridDim.x * blockDim.x;
    const int total = N1 + N2 + N3;
    for (int i = tid0; i < total; i += stride) {
        float4 v;
        uint2* dst;
        int di;
        if (i < N1) {
            v = hs[i]; dst = ohs; di = i;
        } else if (i < N1 + N2) {
            int j = i - N1;
            int row = j / (NQKV / 4);
            int c = j - row * (NQKV / 4);
            if (c < 512)      v = Wq[row * 512 + c];
            else if (c < 640) v = Wk[row * 128 + (c - 512)];
            else              v = Wv[row * 128 + (c - 640)];
            dst = owqkv; di = j;
        } else {
            int j = i - N1 - N2;
            v = Wo[j]; dst = owo; di = j;
        }
        __half2 lo = __floats2half2_rn(v.x, v.y);
        __half2 hi = __floats2half2_rn(v.z, v.w);
        uint2 o;
        o.x = *reinterpret_cast<uint32_t*>(&lo);
        o.y = *reinterpret_cast<uint32_t*>(&hi);
        dst[di] = o;
    }
}

// -------- attention over the replica axis (P=4), round-8 proven version --------
__global__ void __launch_bounds__(128)
attn_kernel(const float* __restrict__ QKV, const float* __restrict__ cosp,
            const float* __restrict__ sinp, __half* __restrict__ ctx)
{
    const int s = blockIdx.x;
    const int b = blockIdx.y;
    const int t = threadIdx.x;
    const int lane = t & 31;
    const int w = t >> 5;  // q replica p

    __shared__ float ksm[2048];  // [p][hk][d]
    __shared__ float vsm[2048];
    __shared__ float cs[512];
    __shared__ float sn[512];

#pragma unroll
    for (int i = t; i < 512; i += 128) {
        cs[i] = cosp[b * 512 + i];
        sn[i] = sinp[b * 512 + i];
    }
#pragma unroll
    for (int j = 0; j < 16; ++j) {
        int i = j * 128 + t;
        int p = i >> 9;
        int col = i & 511;
        size_t row = (size_t)(p * 2 + b) * 2048 + s;
        ksm[i] = QKV[row * NQKV + 2048 + col];
        vsm[i] = QKV[row * NQKV + 2560 + col];
    }
    __syncthreads();

    float kn[16];
#pragma unroll
    for (int j = 0; j < 16; ++j) {
        int i = j * 128 + t;
        int p = j >> 2;
        float c = cs[p * 128 + t];
        float sv = sn[p * 128 + t];
        float a = ksm[i];
        float pr = ksm[i ^ 64];
        kn[j] = a * c + ((t & 64) ? pr : -pr) * sv;
    }
    __syncthreads();
#pragma unroll
    for (int j = 0; j < 16; ++j) ksm[j * 128 + t] = kn[j];
    __syncthreads();

    const size_t qrow = (size_t)(w * 2 + b) * 2048 + s;
    const float c0 = cs[w * 128 + lane],      c1 = cs[w * 128 + lane + 32];
    const float c2 = cs[w * 128 + lane + 64], c3 = cs[w * 128 + lane + 96];
    const float s0 = sn[w * 128 + lane],      s1 = sn[w * 128 + lane + 32];
    const float s2 = sn[w * 128 + lane + 64], s3 = sn[w * 128 + lane + 96];

    for (int h = 0; h < 16; ++h) {
        const int hk = h & 3;
        const float* qp = QKV + qrow * NQKV + h * 128;
        float q0 = qp[lane], q1 = qp[lane + 32], q2 = qp[lane + 64], q3 = qp[lane + 96];
        float qr0 = q0 * c0 - q2 * s0;
        float qr1 = q1 * c1 - q3 * s1;
        float qr2 = q2 * c2 + q0 * s2;
        float qr3 = q3 * c3 + q1 * s3;

        float sc[4];
#pragma unroll
        for (int qq = 0; qq < 4; ++qq) {
            const float* kp = ksm + qq * 512 + hk * 128;
            float part = qr0 * kp[lane] + qr1 * kp[lane + 32] +
                         qr2 * kp[lane + 64] + qr3 * kp[lane + 96];
#pragma unroll
            for (int o = 16; o; o >>= 1)
                part += __shfl_xor_sync(0xffffffffu, part, o);
            sc[qq] = part * 0.088388347648318447f;  // 1/sqrt(128)
        }
        float mx = fmaxf(fmaxf(sc[0], sc[1]), fmaxf(sc[2], sc[3]));
        float e0 = __expf(sc[0] - mx), e1 = __expf(sc[1] - mx);
        float e2 = __expf(sc[2] - mx), e3 = __expf(sc[3] - mx);
        float inv = 1.f / (e0 + e1 + e2 + e3);
        float a0 = e0 * inv, a1 = e1 * inv, a2 = e2 * inv, a3 = e3 * inv;

        const float* v0p = vsm + 0 * 512 + hk * 128;
        const float* v1p = vsm + 1 * 512 + hk * 128;
        const float* v2p = vsm + 2 * 512 + hk * 128;
        const float* v3p = vsm + 3 * 512 + hk * 128;
        float o0 = a0 * v0p[lane]      + a1 * v1p[lane]      + a2 * v2p[lane]      + a3 * v3p[lane];
        float o1 = a0 * v0p[lane + 32] + a1 * v1p[lane + 32] + a2 * v1p[lane + 32] * 0.f + a1 * 0.f + a2 * v2p[lane + 32] + a3 * v3p[lane + 32];
        o1 = a0 * v0p[lane + 32] + a1 * v1p[lane + 32] + a2 * v2p[lane + 32] + a3 * v3p[lane + 32];
        float o2 = a0 * v0p[lane + 64] + a1 * v1p[lane + 64] + a2 * v2p[lane + 64] + a3 * v3p[lane + 64];
        float o3 = a0 * v0p[lane + 96] + a1 * v1p[lane + 96] + a2 * v2p[lane + 96] + a3 * v3p[lane + 96];

        __half* op = ctx + qrow * 2048 + h * 128;
        op[lane]      = __float2half_rn(o0);
        op[lane + 32] = __float2half_rn(o1);
        op[lane + 64] = __float2half_rn(o2);
        op[lane + 96] = __float2half_rn(o3);
    }
}

// -------- launch --------
extern "C" void kernel_launch(void* const* d_in, const int* in_sizes, int n_in,
                              void* d_out, int out_size)
{
    const float* hs   = (const float*)d_in[0];
    const float* cosp = (const float*)d_in[1];
    const float* sinp = (const float*)d_in[2];
    const float* Wq   = (const float*)d_in[3];
    const float* bq   = (const float*)d_in[4];
    const float* Wk   = (const float*)d_in[5];
    const float* bk   = (const float*)d_in[6];
    const float* Wv   = (const float*)d_in[7];
    const float* bv   = (const float*)d_in[8];
    const float* Wo   = (const float*)d_in[9];
    float* out = (float*)d_out;

    void *phs, *pwqkv, *pwo, *pctx, *pqkv, *pb;
    cudaGetSymbolAddress(&phs, g_hs_h);
    cudaGetSymbolAddress(&pwqkv, g_wqkv_h);
    cudaGetSymbolAddress(&pwo, g_wo_h);
    cudaGetSymbolAddress(&pctx, g_ctx_h);
    cudaGetSymbolAddress(&pqkv, g_qkv);
    cudaGetSymbolAddress(&pb, g_bias);

    cudaFuncSetAttribute(gemm_h, cudaFuncAttributeMaxDynamicSharedMemorySize, SMEM_BYTES);

    // one fused conversion / packing pass
    conv_all<<<2048, 256>>>((const float4*)hs,
                            (const float4*)Wq, (const float4*)Wk, (const float4*)Wv,
                            (const float4*)Wo, bq, bk, bv,
                            (uint2*)phs, (uint2*)pwqkv, (uint2*)pwo, (float*)pb);

    // fused QKV projection: [M,2048] @ [2048,3072]
    gemm_h<<<dim3(NQKV / BN, M_ROWS / BM), 128, SMEM_BYTES>>>(
        (const __half*)phs, (const __half*)pwqkv, (const float*)pb, (float*)pqkv, NQKV);

    // replica attention (writes fp16 ctx)
    attn_kernel<<<dim3(2048, 2), 128>>>((const float*)pqkv, cosp, sinp, (__half*)pctx);

    // output projection
    gemm_h<<<dim3(2048 / BN, M_ROWS / BM), 128, SMEM_BYTES>>>(
        (const __half*)pctx, (const __half*)pwo, nullptr, out, 2048);
}

// round 13
// speedup vs baseline: 1.3196x; 1.3196x over previous
#include <cuda_runtime.h>
#include <cuda_fp16.h>
#include <cstdint>

// Problem: P=4, B=2, S=2048, D=2048, H=16, HK=4, DH=128, G=4
#define M_ROWS 16384
#define KD     2048
#define NQKV   3072   // 2048 q | 512 k | 512 v

// -------- scratch (device globals: allocation-free) --------
__device__ __half g_hs_h[(size_t)M_ROWS * KD];
__device__ __half g_wqkv_h[(size_t)KD * NQKV];
__device__ __half g_wo_h[(size_t)2048 * 2048];
__device__ __half g_ctx_h[(size_t)M_ROWS * 2048];
__device__ float  g_qkv[(size_t)M_ROWS * NQKV];
__device__ float  g_bias[NQKV];

// -------- GEMM config (round-11 measured-best) --------
#define BM 128
#define BN 128
#define BK 32                  // halves per k-stage
#define NTILE (KD / BK)        // 64
#define STAGES 4
#define ASTR 40                // halves per A smem row (80B)
#define BSTR 136               // halves per B smem row (272B)
#define A_STAGE (BM * ASTR)    // 5120 halves
#define B_STAGE (BK * BSTR)    // 4352 halves
#define SMEM_BYTES (STAGES * (A_STAGE + B_STAGE) * 2)   // 75776

// -------- PTX helpers --------
__device__ __forceinline__ uint32_t s2u(const void* p) {
    uint32_t a;
    asm("{ .reg .u64 t; cvta.to.shared.u64 t, %1; cvt.u32.u64 %0, t; }" : "=r"(a) : "l"(p));
    return a;
}
__device__ __forceinline__ void cp16(uint32_t dst, const void* src) {
    asm volatile("cp.async.cg.shared.global [%0], [%1], 16;" :: "r"(dst), "l"(src));
}
__device__ __forceinline__ void cp_commit() {
    asm volatile("cp.async.commit_group;" ::: "memory");
}
__device__ __forceinline__ void ldsm4(uint32_t* r, uint32_t addr) {
    asm volatile("ldmatrix.sync.aligned.m8n8.x4.shared.b16 {%0,%1,%2,%3}, [%4];"
        : "=r"(r[0]), "=r"(r[1]), "=r"(r[2]), "=r"(r[3]) : "r"(addr));
}
__device__ __forceinline__ void ldsm4t(uint32_t* r, uint32_t addr) {
    asm volatile("ldmatrix.sync.aligned.m8n8.x4.trans.shared.b16 {%0,%1,%2,%3}, [%4];"
        : "=r"(r[0]), "=r"(r[1]), "=r"(r[2]), "=r"(r[3]) : "r"(addr));
}
// non-volatile — lets ptxas interleave HMMAs with later LDSMs.
__device__ __forceinline__ void mma_h(float* c, const uint32_t* a, const uint32_t* b) {
    asm("mma.sync.aligned.m16n8k16.row.col.f32.f16.f16.f32 "
        "{%0,%1,%2,%3}, {%4,%5,%6,%7}, {%8,%9}, {%0,%1,%2,%3};"
        : "+f"(c[0]), "+f"(c[1]), "+f"(c[2]), "+f"(c[3])
        : "r"(a[0]), "r"(a[1]), "r"(a[2]), "r"(a[3]), "r"(b[0]), "r"(b[1]));
}

// -------- fp16 tensor-core GEMM: C[M,N](f32) = A[M,K](f16) @ B[K,N](f16) (+bias) --------
// Round-11 winner + LDSM-order skew + prefetch split across the two kk passes.
__global__ void __launch_bounds__(256, 2)
gemm_h(const __half* __restrict__ A, const __half* __restrict__ B,
       const float* __restrict__ bias, float* __restrict__ C, int N)
{
    extern __shared__ __half sm[];
    __half* sA = sm;
    __half* sB = sm + STAGES * A_STAGE;

    const int t = threadIdx.x, lane = t & 31, warp = t >> 5;
    const int wm = warp >> 2, wn = warp & 3;      // 2 x 4 warp grid, warp tile 64x32
    const int g = lane >> 2, tg = lane & 3;
    const int bm = blockIdx.y * BM, bn = blockIdx.x * BN;

    // cp.async staging map
    const int ar = t >> 1;              // A row 0..127
    const int ac = (t & 1) * 16;        // halves 0 / 16
    const int br = t >> 3;              // B row 0..31
    const int bc = (t & 7) * 16;        // halves 0..112

    const __half* Ag = A + (size_t)(bm + ar) * KD + ac;
    const __half* Bg = B + (size_t)br * N + bn + bc;

    // ---- precomputed integer SMEM addresses (bytes) ----
    const uint32_t sAu = s2u(sA);
    const uint32_t sBu = s2u(sB);
    const uint32_t daBase = sAu + (uint32_t)(ar * ASTR + ac) * 2;
    const uint32_t dbBase = sBu + (uint32_t)(br * BSTR + bc) * 2;
    const int a_row = (lane & 15);
    const int a_col = ((lane >> 4) << 3);
    const int b_row = (lane & 7) + (((lane >> 3) & 1) << 3);
    const int b_col = ((lane >> 4) << 3);
    const uint32_t aW = sAu + (uint32_t)((wm * 64 + a_row) * ASTR + a_col) * 2;
    const uint32_t bW = sBu + (uint32_t)(b_row * BSTR + wn * 32 + b_col) * 2;

    const int kk0 = warp & 1;           // phase skew: odd warps start at kk=1

    float acc[4][4][4];
#pragma unroll
    for (int i = 0; i < 4; i++)
#pragma unroll
        for (int j = 0; j < 4; j++)
#pragma unroll
            for (int l = 0; l < 4; l++) acc[i][j][l] = 0.f;

    // prologue: issue STAGES-1 stages
#pragma unroll
    for (int s = 0; s < STAGES - 1; s++) {
        const uint32_t da = daBase + s * (A_STAGE * 2);
        const __half* Ap = Ag + s * BK;
        cp16(da, Ap); cp16(da + 16, Ap + 8);
        const uint32_t db = dbBase + s * (B_STAGE * 2);
        const __half* Bp = Bg + (size_t)s * BK * N;
        cp16(db, Bp); cp16(db + 16, Bp + 8);
        cp_commit();
    }

    for (int kt = 0; kt < NTILE; kt++) {
        const int s = kt & (STAGES - 1);
        asm volatile("cp.async.wait_group %0;" :: "n"(STAGES - 2));
        __syncthreads();

        const uint32_t aS = aW + s * (A_STAGE * 2);
        const uint32_t bS = bW + s * (B_STAGE * 2);
        const bool pf = (kt + STAGES - 1 < NTILE);
        const int sn = (kt + STAGES - 1) & (STAGES - 1);

#pragma unroll
        for (int pass = 0; pass < 2; pass++) {
            const int kk = kk0 ^ pass;
            const uint32_t aK = aS + kk * 32;
            const uint32_t bK = bS + kk * (16 * BSTR * 2);

            uint32_t bf[4][2];
            uint32_t af[4][4];
            if (kk0) {
                // odd warps: A fragments first
#pragma unroll
                for (int mt = 0; mt < 4; mt++)
                    ldsm4(af[mt], aK + mt * (16 * ASTR * 2));
#pragma unroll
                for (int nt2 = 0; nt2 < 2; nt2++) {
                    uint32_t rr[4];
                    ldsm4t(rr, bK + nt2 * 32);
                    bf[nt2 * 2][0] = rr[0]; bf[nt2 * 2][1] = rr[1];
                    bf[nt2 * 2 + 1][0] = rr[2]; bf[nt2 * 2 + 1][1] = rr[3];
                }
            } else {
                // even warps: B fragments first
#pragma unroll
                for (int nt2 = 0; nt2 < 2; nt2++) {
                    uint32_t rr[4];
                    ldsm4t(rr, bK + nt2 * 32);
                    bf[nt2 * 2][0] = rr[0]; bf[nt2 * 2][1] = rr[1];
                    bf[nt2 * 2 + 1][0] = rr[2]; bf[nt2 * 2 + 1][1] = rr[3];
                }
#pragma unroll
                for (int mt = 0; mt < 4; mt++)
                    ldsm4(af[mt], aK + mt * (16 * ASTR * 2));
            }
#pragma unroll
            for (int mt = 0; mt < 4; mt++)
#pragma unroll
                for (int nt = 0; nt < 4; nt++)
                    mma_h(acc[mt][nt], af[mt], bf[nt]);

            // prefetch split: A half in pass 0, B half + commit in pass 1
            if (pass == 0) {
                if (pf) {
                    const uint32_t da = daBase + sn * (A_STAGE * 2);
                    const __half* Ap = Ag + (kt + STAGES - 1) * BK;
                    cp16(da, Ap); cp16(da + 16, Ap + 8);
                }
            } else {
                if (pf) {
                    const uint32_t db = dbBase + sn * (B_STAGE * 2);
                    const __half* Bp = Bg + (size_t)(kt + STAGES - 1) * BK * N;
                    cp16(db, Bp); cp16(db + 16, Bp + 8);
                    cp_commit();
                }
            }
        }
    }

    // epilogue
#pragma unroll
    for (int mt = 0; mt < 4; mt++) {
        const int r0 = bm + wm * 64 + mt * 16 + g;
#pragma unroll
        for (int nt = 0; nt < 4; nt++) {
            const int c0 = bn + wn * 32 + nt * 8 + tg * 2;
            float bb0 = bias ? bias[c0] : 0.f;
            float bb1 = bias ? bias[c0 + 1] : 0.f;
            float2 v0 = make_float2(acc[mt][nt][0] + bb0, acc[mt][nt][1] + bb1);
            float2 v1 = make_float2(acc[mt][nt][2] + bb0, acc[mt][nt][3] + bb1);
            *(float2*)(C + (size_t)r0 * N + c0) = v0;
            *(float2*)(C + (size_t)(r0 + 8) * N + c0) = v1;
        }
    }
}

// -------- single fused conversion / packing kernel --------
#define N1 8388608
#define N2 1572864
#define N3 1048576
__global__ void conv_all(const float4* __restrict__ hs,
                         const float4* __restrict__ Wq, const float4* __restrict__ Wk,
                         const float4* __restrict__ Wv, const float4* __restrict__ Wo,
                         const float* __restrict__ bq, const float* __restrict__ bk,
                         const float* __restrict__ bv,
                         uint2* __restrict__ ohs, uint2* __restrict__ owqkv,
                         uint2* __restrict__ owo, float* __restrict__ obias)
{
    const int tid0 = blockIdx.x * blockDim.x + threadIdx.x;
    if (tid0 < NQKV)
        obias[tid0] = (tid0 < 2048) ? bq[tid0] : (tid0 < 2560) ? bk[tid0 - 2048] : bv[tid0 - 2560];

    const int stride = gridDim.x * blockDim.x;
    const int total = N1 + N2 + N3;
    for (int i = tid0; i < total; i += stride) {
        float4 v;
        uint2* dst;
        int di;
        if (i < N1) {
            v = hs[i]; dst = ohs; di = i;
        } else if (i < N1 + N2) {
            int j = i - N1;
            int row = j / (NQKV / 4);
            int c = j - row * (NQKV / 4);
            if (c < 512)      v = Wq[row * 512 + c];
            else if (c < 640) v = Wk[row * 128 + (c - 512)];
            else              v = Wv[row * 128 + (c - 640)];
            dst = owqkv; di = j;
        } else {
            int j = i - N1 - N2;
            v = Wo[j]; dst = owo; di = j;
        }
        __half2 lo = __floats2half2_rn(v.x, v.y);
        __half2 hi = __floats2half2_rn(v.z, v.w);
        uint2 o;
        o.x = *reinterpret_cast<uint32_t*>(&lo);
        o.y = *reinterpret_cast<uint32_t*>(&hi);
        dst[di] = o;
    }
}

// -------- attention over the replica axis (P=4), round-8 proven version --------
__global__ void __launch_bounds__(128)
attn_kernel(const float* __restrict__ QKV, const float* __restrict__ cosp,
            const float* __restrict__ sinp, __half* __restrict__ ctx)
{
    const int s = blockIdx.x;
    const int b = blockIdx.y;
    const int t = threadIdx.x;
    const int lane = t & 31;
    const int w = t >> 5;  // q replica p

    __shared__ float ksm[2048];  // [p][hk][d]
    __shared__ float vsm[2048];
    __shared__ float cs[512];
    __shared__ float sn[512];

#pragma unroll
    for (int i = t; i < 512; i += 128) {
        cs[i] = cosp[b * 512 + i];
        sn[i] = sinp[b * 512 + i];
    }
#pragma unroll
    for (int j = 0; j < 16; ++j) {
        int i = j * 128 + t;
        int p = i >> 9;
        int col = i & 511;
        size_t row = (size_t)(p * 2 + b) * 2048 + s;
        ksm[i] = QKV[row * NQKV + 2048 + col];
        vsm[i] = QKV[row * NQKV + 2560 + col];
    }
    __syncthreads();

    float kn[16];
#pragma unroll
    for (int j = 0; j < 16; ++j) {
        int i = j * 128 + t;
        int p = j >> 2;
        float c = cs[p * 128 + t];
        float sv = sn[p * 128 + t];
        float a = ksm[i];
        float pr = ksm[i ^ 64];
        kn[j] = a * c + ((t & 64) ? pr : -pr) * sv;
    }
    __syncthreads();
#pragma unroll
    for (int j = 0; j < 16; ++j) ksm[j * 128 + t] = kn[j];
    __syncthreads();

    const size_t qrow = (size_t)(w * 2 + b) * 2048 + s;
    const float c0 = cs[w * 128 + lane],      c1 = cs[w * 128 + lane + 32];
    const float c2 = cs[w * 128 + lane + 64], c3 = cs[w * 128 + lane + 96];
    const float s0 = sn[w * 128 + lane],      s1 = sn[w * 128 + lane + 32];
    const float s2 = sn[w * 128 + lane + 64], s3 = sn[w * 128 + lane + 96];

    for (int h = 0; h < 16; ++h) {
        const int hk = h & 3;
        const float* qp = QKV + qrow * NQKV + h * 128;
        float q0 = qp[lane], q1 = qp[lane + 32], q2 = qp[lane + 64], q3 = qp[lane + 96];
        float qr0 = q0 * c0 - q2 * s0;
        float qr1 = q1 * c1 - q3 * s1;
        float qr2 = q2 * c2 + q0 * s2;
        float qr3 = q3 * c3 + q1 * s3;

        float sc[4];
#pragma unroll
        for (int qq = 0; qq < 4; ++qq) {
            const float* kp = ksm + qq * 512 + hk * 128;
            float part = qr0 * kp[lane] + qr1 * kp[lane + 32] +
                         qr2 * kp[lane + 64] + qr3 * kp[lane + 96];
#pragma unroll
            for (int o = 16; o; o >>= 1)
                part += __shfl_xor_sync(0xffffffffu, part, o);
            sc[qq] = part * 0.088388347648318447f;  // 1/sqrt(128)
        }
        float mx = fmaxf(fmaxf(sc[0], sc[1]), fmaxf(sc[2], sc[3]));
        float e0 = __expf(sc[0] - mx), e1 = __expf(sc[1] - mx);
        float e2 = __expf(sc[2] - mx), e3 = __expf(sc[3] - mx);
        float inv = 1.f / (e0 + e1 + e2 + e3);
        float a0 = e0 * inv, a1 = e1 * inv, a2 = e2 * inv, a3 = e3 * inv;

        const float* v0p = vsm + 0 * 512 + hk * 128;
        const float* v1p = vsm + 1 * 512 + hk * 128;
        const float* v2p = vsm + 2 * 512 + hk * 128;
        const float* v3p = vsm + 3 * 512 + hk * 128;
        float o0 = a0 * v0p[lane]      + a1 * v1p[lane]      + a2 * v2p[lane]      + a3 * v3p[lane];
        float o1 = a0 * v0p[lane + 32] + a1 * v1p[lane + 32] + a2 * v2p[lane + 32] + a3 * v3p[lane + 32];
        float o2 = a0 * v0p[lane + 64] + a1 * v1p[lane + 64] + a2 * v2p[lane + 64] + a3 * v3p[lane + 64];
        float o3 = a0 * v0p[lane + 96] + a1 * v1p[lane + 96] + a2 * v2p[lane + 96] + a3 * v3p[lane + 96];

        __half* op = ctx + qrow * 2048 + h * 128;
        op[lane]      = __float2half_rn(o0);
        op[lane + 32] = __float2half_rn(o1);
        op[lane + 64] = __float2half_rn(o2);
        op[lane + 96] = __float2half_rn(o3);
    }
}

// -------- launch --------
extern "C" void kernel_launch(void* const* d_in, const int* in_sizes, int n_in,
                              void* d_out, int out_size)
{
    const float* hs   = (const float*)d_in[0];
    const float* cosp = (const float*)d_in[1];
    const float* sinp = (const float*)d_in[2];
    const float* Wq   = (const float*)d_in[3];
    const float* bq   = (const float*)d_in[4];
    const float* Wk   = (const float*)d_in[5];
    const float* bk   = (const float*)d_in[6];
    const float* Wv   = (const float*)d_in[7];
    const float* bv   = (const float*)d_in[8];
    const float* Wo   = (const float*)d_in[9];
    float* out = (float*)d_out;

    void *phs, *pwqkv, *pwo, *pctx, *pqkv, *pb;
    cudaGetSymbolAddress(&phs, g_hs_h);
    cudaGetSymbolAddress(&pwqkv, g_wqkv_h);
    cudaGetSymbolAddress(&pwo, g_wo_h);
    cudaGetSymbolAddress(&pctx, g_ctx_h);
    cudaGetSymbolAddress(&pqkv, g_qkv);
    cudaGetSymbolAddress(&pb, g_bias);

    cudaFuncSetAttribute(gemm_h, cudaFuncAttributeMaxDynamicSharedMemorySize, SMEM_BYTES);

    // one fused conversion / packing pass
    conv_all<<<2048, 256>>>((const float4*)hs,
                            (const float4*)Wq, (const float4*)Wk, (const float4*)Wv,
                            (const float4*)Wo, bq, bk, bv,
                            (uint2*)phs, (uint2*)pwqkv, (uint2*)pwo, (float*)pb);

    // fused QKV projection: [M,2048] @ [2048,3072]
    gemm_h<<<dim3(NQKV / BN, M_ROWS / BM), 256, SMEM_BYTES>>>(
        (const __half*)phs, (const __half*)pwqkv, (const float*)pb, (float*)pqkv, NQKV);

    // replica attention (writes fp16 ctx)
    attn_kernel<<<dim3(2048, 2), 128>>>((const float*)pqkv, cosp, sinp, (__half*)pctx);

    // output projection
    gemm_h<<<dim3(2048 / BN, M_ROWS / BM), 256, SMEM_BYTES>>>(
        (const __half*)pctx, (const __half*)pwo, nullptr, out, 2048);
}

// round 14
// speedup vs baseline: 1.4522x; 1.1005x over previous
#include <cuda_runtime.h>
#include <cuda_fp16.h>
#include <cstdint>

// Problem: P=4, B=2, S=2048, D=2048, H=16, HK=4, DH=128, G=4
#define M_ROWS 16384
#define KD     2048
#define NQKV   3072   // 2048 q | 512 k | 512 v

// -------- scratch (device globals: allocation-free) --------
__device__ __half g_hs_h[(size_t)M_ROWS * KD];
__device__ __half g_wqkv_h[(size_t)KD * NQKV];
__device__ __half g_wo_h[(size_t)2048 * 2048];
__device__ __half g_ctx_h[(size_t)M_ROWS * 2048];
__device__ __half g_qkv_h[(size_t)M_ROWS * NQKV];
__device__ float  g_bias[NQKV];

// -------- GEMM config (round-11 measured-best; mainloop FROZEN) --------
#define BM 128
#define BN 128
#define BK 32                  // halves per k-stage
#define NTILE (KD / BK)        // 64
#define STAGES 4
#define ASTR 40                // halves per A smem row (80B)
#define BSTR 136               // halves per B smem row (272B)
#define A_STAGE (BM * ASTR)    // 5120 halves
#define B_STAGE (BK * BSTR)    // 4352 halves
#define SMEM_BYTES (STAGES * (A_STAGE + B_STAGE) * 2)   // 75776

// -------- PTX helpers --------
__device__ __forceinline__ uint32_t s2u(const void* p) {
    uint32_t a;
    asm("{ .reg .u64 t; cvta.to.shared.u64 t, %1; cvt.u32.u64 %0, t; }" : "=r"(a) : "l"(p));
    return a;
}
__device__ __forceinline__ void cp16(uint32_t dst, const void* src) {
    asm volatile("cp.async.cg.shared.global [%0], [%1], 16;" :: "r"(dst), "l"(src));
}
__device__ __forceinline__ void cp_commit() {
    asm volatile("cp.async.commit_group;" ::: "memory");
}
__device__ __forceinline__ void ldsm4(uint32_t* r, uint32_t addr) {
    asm volatile("ldmatrix.sync.aligned.m8n8.x4.shared.b16 {%0,%1,%2,%3}, [%4];"
        : "=r"(r[0]), "=r"(r[1]), "=r"(r[2]), "=r"(r[3]) : "r"(addr));
}
__device__ __forceinline__ void ldsm4t(uint32_t* r, uint32_t addr) {
    asm volatile("ldmatrix.sync.aligned.m8n8.x4.trans.shared.b16 {%0,%1,%2,%3}, [%4];"
        : "=r"(r[0]), "=r"(r[1]), "=r"(r[2]), "=r"(r[3]) : "r"(addr));
}
// non-volatile — lets ptxas interleave HMMAs with later LDSMs.
__device__ __forceinline__ void mma_h(float* c, const uint32_t* a, const uint32_t* b) {
    asm("mma.sync.aligned.m16n8k16.row.col.f32.f16.f16.f32 "
        "{%0,%1,%2,%3}, {%4,%5,%6,%7}, {%8,%9}, {%0,%1,%2,%3};"
        : "+f"(c[0]), "+f"(c[1]), "+f"(c[2]), "+f"(c[3])
        : "r"(a[0]), "r"(a[1]), "r"(a[2]), "r"(a[3]), "r"(b[0]), "r"(b[1]));
}

// -------- fp16 tensor-core GEMM (round-11 mainloop verbatim) --------
// half_out: 0 = write float C, 1 = write __half C (after fp32 bias add)
__global__ void __launch_bounds__(256, 2)
gemm_h(const __half* __restrict__ A, const __half* __restrict__ B,
       const float* __restrict__ bias, void* __restrict__ Cv, int N, int half_out)
{
    extern __shared__ __half sm[];
    __half* sA = sm;
    __half* sB = sm + STAGES * A_STAGE;

    const int t = threadIdx.x, lane = t & 31, warp = t >> 5;
    const int wm = warp >> 2, wn = warp & 3;      // 2 x 4 warp grid, warp tile 64x32
    const int g = lane >> 2, tg = lane & 3;
    const int bm = blockIdx.y * BM, bn = blockIdx.x * BN;

    // cp.async staging map
    const int ar = t >> 1;              // A row 0..127
    const int ac = (t & 1) * 16;        // halves 0 / 16
    const int br = t >> 3;              // B row 0..31
    const int bc = (t & 7) * 16;        // halves 0..112

    const __half* Ag = A + (size_t)(bm + ar) * KD + ac;
    const __half* Bg = B + (size_t)br * N + bn + bc;

    // ---- precomputed integer SMEM addresses (bytes) ----
    const uint32_t sAu = s2u(sA);
    const uint32_t sBu = s2u(sB);
    const uint32_t daBase = sAu + (uint32_t)(ar * ASTR + ac) * 2;
    const uint32_t dbBase = sBu + (uint32_t)(br * BSTR + bc) * 2;
    const int a_row = (lane & 15);
    const int a_col = ((lane >> 4) << 3);
    const int b_row = (lane & 7) + (((lane >> 3) & 1) << 3);
    const int b_col = ((lane >> 4) << 3);
    const uint32_t aW = sAu + (uint32_t)((wm * 64 + a_row) * ASTR + a_col) * 2;
    const uint32_t bW = sBu + (uint32_t)(b_row * BSTR + wn * 32 + b_col) * 2;

    const int kk0 = warp & 1;           // phase skew: odd warps start at kk=1

    float acc[4][4][4];
#pragma unroll
    for (int i = 0; i < 4; i++)
#pragma unroll
        for (int j = 0; j < 4; j++)
#pragma unroll
            for (int l = 0; l < 4; l++) acc[i][j][l] = 0.f;

    // prologue: issue STAGES-1 stages
#pragma unroll
    for (int s = 0; s < STAGES - 1; s++) {
        const uint32_t da = daBase + s * (A_STAGE * 2);
        const __half* Ap = Ag + s * BK;
        cp16(da, Ap); cp16(da + 16, Ap + 8);
        const uint32_t db = dbBase + s * (B_STAGE * 2);
        const __half* Bp = Bg + (size_t)s * BK * N;
        cp16(db, Bp); cp16(db + 16, Bp + 8);
        cp_commit();
    }

    for (int kt = 0; kt < NTILE; kt++) {
        const int s = kt & (STAGES - 1);
        asm volatile("cp.async.wait_group %0;" :: "n"(STAGES - 2));
        __syncthreads();

        const uint32_t aS = aW + s * (A_STAGE * 2);
        const uint32_t bS = bW + s * (B_STAGE * 2);

#pragma unroll
        for (int pass = 0; pass < 2; pass++) {
            const int kk = kk0 ^ pass;
            const uint32_t aK = aS + kk * 32;
            const uint32_t bK = bS + kk * (16 * BSTR * 2);
            uint32_t bf[4][2];
#pragma unroll
            for (int nt2 = 0; nt2 < 2; nt2++) {
                uint32_t rr[4];
                ldsm4t(rr, bK + nt2 * 32);
                bf[nt2 * 2][0] = rr[0]; bf[nt2 * 2][1] = rr[1];
                bf[nt2 * 2 + 1][0] = rr[2]; bf[nt2 * 2 + 1][1] = rr[3];
            }
            uint32_t af[4][4];
#pragma unroll
            for (int mt = 0; mt < 4; mt++)
                ldsm4(af[mt], aK + mt * (16 * ASTR * 2));
#pragma unroll
            for (int mt = 0; mt < 4; mt++)
#pragma unroll
                for (int nt = 0; nt < 4; nt++)
                    mma_h(acc[mt][nt], af[mt], bf[nt]);

            // prefetch issued between the two kk passes (de-phased smem writes)
            if (pass == 0 && kt + STAGES - 1 < NTILE) {
                const int sn = (kt + STAGES - 1) & (STAGES - 1);
                const uint32_t da = daBase + sn * (A_STAGE * 2);
                const __half* Ap = Ag + (kt + STAGES - 1) * BK;
                cp16(da, Ap); cp16(da + 16, Ap + 8);
                const uint32_t db = dbBase + sn * (B_STAGE * 2);
                const __half* Bp = Bg + (size_t)(kt + STAGES - 1) * BK * N;
                cp16(db, Bp); cp16(db + 16, Bp + 8);
                cp_commit();
            }
        }
    }

    // epilogue (fp32 accumulate + bias; optional fp16 store)
#pragma unroll
    for (int mt = 0; mt < 4; mt++) {
        const int r0 = bm + wm * 64 + mt * 16 + g;
#pragma unroll
        for (int nt = 0; nt < 4; nt++) {
            const int c0 = bn + wn * 32 + nt * 8 + tg * 2;
            float bb0 = bias ? bias[c0] : 0.f;
            float bb1 = bias ? bias[c0 + 1] : 0.f;
            const float x0 = acc[mt][nt][0] + bb0, x1 = acc[mt][nt][1] + bb1;
            const float x2 = acc[mt][nt][2] + bb0, x3 = acc[mt][nt][3] + bb1;
            if (half_out) {
                __half* Ch = (__half*)Cv;
                *(__half2*)(Ch + (size_t)r0 * N + c0)       = __floats2half2_rn(x0, x1);
                *(__half2*)(Ch + (size_t)(r0 + 8) * N + c0) = __floats2half2_rn(x2, x3);
            } else {
                float* Cf = (float*)Cv;
                *(float2*)(Cf + (size_t)r0 * N + c0)       = make_float2(x0, x1);
                *(float2*)(Cf + (size_t)(r0 + 8) * N + c0) = make_float2(x2, x3);
            }
        }
    }
}

// -------- single fused conversion / packing kernel --------
#define N1 8388608
#define N2 1572864
#define N3 1048576
__global__ void conv_all(const float4* __restrict__ hs,
                         const float4* __restrict__ Wq, const float4* __restrict__ Wk,
                         const float4* __restrict__ Wv, const float4* __restrict__ Wo,
                         const float* __restrict__ bq, const float* __restrict__ bk,
                         const float* __restrict__ bv,
                         uint2* __restrict__ ohs, uint2* __restrict__ owqkv,
                         uint2* __restrict__ owo, float* __restrict__ obias)
{
    const int tid0 = blockIdx.x * blockDim.x + threadIdx.x;
    if (tid0 < NQKV)
        obias[tid0] = (tid0 < 2048) ? bq[tid0] : (tid0 < 2560) ? bk[tid0 - 2048] : bv[tid0 - 2560];

    const int stride = gridDim.x * blockDim.x;
    const int total = N1 + N2 + N3;
    for (int i = tid0; i < total; i += stride) {
        float4 v;
        uint2* dst;
        int di;
        if (i < N1) {
            v = hs[i]; dst = ohs; di = i;
        } else if (i < N1 + N2) {
            int j = i - N1;
            int row = j / (NQKV / 4);
            int c = j - row * (NQKV / 4);
            if (c < 512)      v = Wq[row * 512 + c];
            else if (c < 640) v = Wk[row * 128 + (c - 512)];
            else              v = Wv[row * 128 + (c - 640)];
            dst = owqkv; di = j;
        } else {
            int j = i - N1 - N2;
            v = Wo[j]; dst = owo; di = j;
        }
        __half2 lo = __floats2half2_rn(v.x, v.y);
        __half2 hi = __floats2half2_rn(v.z, v.w);
        uint2 o;
        o.x = *reinterpret_cast<uint32_t*>(&lo);
        o.y = *reinterpret_cast<uint32_t*>(&hi);
        dst[di] = o;
    }
}

// -------- attention over the replica axis (P=4), fp16 QKV in / fp16 ctx out --------
// QKV layout: [M, 3072] fp16; q = cols 0..2047, k = 2048..2559, v = 2560..3071
__global__ void __launch_bounds__(128)
attn_kernel(const __half* __restrict__ QKV, const float* __restrict__ cosp,
            const float* __restrict__ sinp, __half* __restrict__ ctx)
{
    const int s = blockIdx.x;
    const int b = blockIdx.y;
    const int t = threadIdx.x;
    const int lane = t & 31;
    const int w = t >> 5;  // q replica p

    __shared__ float ksm[2048];  // [p][hk][d]
    __shared__ float vsm[2048];
    __shared__ float cs[512];
    __shared__ float sn[512];

#pragma unroll
    for (int i = t; i < 512; i += 128) {
        cs[i] = cosp[b * 512 + i];
        sn[i] = sinp[b * 512 + i];
    }
    // K/V fill: each p-row is 512 halves = 1024 B; 128 threads x uint2 (4 halves) = one pass
#pragma unroll
    for (int p = 0; p < 4; ++p) {
        const size_t row = (size_t)(p * 2 + b) * 2048 + s;
        const uint2 kv = *(const uint2*)(QKV + row * NQKV + 2048 + t * 4);
        const uint2 vv = *(const uint2*)(QKV + row * NQKV + 2560 + t * 4);
        const __half2 k01 = *(const __half2*)&kv.x;
        const __half2 k23 = *(const __half2*)&kv.y;
        const __half2 v01 = *(const __half2*)&vv.x;
        const __half2 v23 = *(const __half2*)&vv.y;
        float* kd = ksm + p * 512 + t * 4;
        float* vd = vsm + p * 512 + t * 4;
        kd[0] = __half2float(k01.x); kd[1] = __half2float(k01.y);
        kd[2] = __half2float(k23.x); kd[3] = __half2float(k23.y);
        vd[0] = __half2float(v01.x); vd[1] = __half2float(v01.y);
        vd[2] = __half2float(v23.x); vd[3] = __half2float(v23.y);
    }
    __syncthreads();

    // RoPE K in shared (d == t since 128 threads; partner d^64)
    float kn[16];
#pragma unroll
    for (int j = 0; j < 16; ++j) {
        int i = j * 128 + t;
        int p = j >> 2;
        float c = cs[p * 128 + t];
        float sv = sn[p * 128 + t];
        float a = ksm[i];
        float pr = ksm[i ^ 64];
        kn[j] = a * c + ((t & 64) ? pr : -pr) * sv;
    }
    __syncthreads();
#pragma unroll
    for (int j = 0; j < 16; ++j) ksm[j * 128 + t] = kn[j];
    __syncthreads();

    const size_t qrow = (size_t)(w * 2 + b) * 2048 + s;
    const float c0 = cs[w * 128 + lane],      c1 = cs[w * 128 + lane + 32];
    const float c2 = cs[w * 128 + lane + 64], c3 = cs[w * 128 + lane + 96];
    const float s0 = sn[w * 128 + lane],      s1 = sn[w * 128 + lane + 32];
    const float s2 = sn[w * 128 + lane + 64], s3 = sn[w * 128 + lane + 96];

    for (int h = 0; h < 16; ++h) {
        const int hk = h & 3;
        const __half* qp = QKV + qrow * NQKV + h * 128;
        float q0 = __half2float(qp[lane]);
        float q1 = __half2float(qp[lane + 32]);
        float q2 = __half2float(qp[lane + 64]);
        float q3 = __half2float(qp[lane + 96]);
        float qr0 = q0 * c0 - q2 * s0;
        float qr1 = q1 * c1 - q3 * s1;
        float qr2 = q2 * c2 + q0 * s2;
        float qr3 = q3 * c3 + q1 * s3;

        float sc[4];
#pragma unroll
        for (int qq = 0; qq < 4; ++qq) {
            const float* kp = ksm + qq * 512 + hk * 128;
            float part = qr0 * kp[lane] + qr1 * kp[lane + 32] +
                         qr2 * kp[lane + 64] + qr3 * kp[lane + 96];
#pragma unroll
            for (int o = 16; o; o >>= 1)
                part += __shfl_xor_sync(0xffffffffu, part, o);
            sc[qq] = part * 0.088388347648318447f;  // 1/sqrt(128)
        }
        float mx = fmaxf(fmaxf(sc[0], sc[1]), fmaxf(sc[2], sc[3]));
        float e0 = __expf(sc[0] - mx), e1 = __expf(sc[1] - mx);
        float e2 = __expf(sc[2] - mx), e3 = __expf(sc[3] - mx);
        float inv = 1.f / (e0 + e1 + e2 + e3);
        float a0 = e0 * inv, a1 = e1 * inv, a2 = e2 * inv, a3 = e3 * inv;

        const float* v0p = vsm + 0 * 512 + hk * 128;
        const float* v1p = vsm + 1 * 512 + hk * 128;
        const float* v2p = vsm + 2 * 512 + hk * 128;
        const float* v3p = vsm + 3 * 512 + hk * 128;
        float o0 = a0 * v0p[lane]      + a1 * v1p[lane]      + a2 * v2p[lane]      + a3 * v3p[lane];
        float o1 = a0 * v0p[lane + 32] + a1 * v1p[lane + 32] + a2 * v2p[lane + 32] + a3 * v3p[lane + 32];
        float o2 = a0 * v0p[lane + 64] + a1 * v1p[lane + 64] + a2 * v2p[lane + 64] + a3 * v3p[lane + 64];
        float o3 = a0 * v0p[lane + 96] + a1 * v1p[lane + 96] + a2 * v2p[lane + 96] + a3 * v3p[lane + 96];

        __half* op = ctx + qrow * 2048 + h * 128;
        op[lane]      = __float2half_rn(o0);
        op[lane + 32] = __float2half_rn(o1);
        op[lane + 64] = __float2half_rn(o2);
        op[lane + 96] = __float2half_rn(o3);
    }
}

// -------- launch --------
extern "C" void kernel_launch(void* const* d_in, const int* in_sizes, int n_in,
                              void* d_out, int out_size)
{
    const float* hs   = (const float*)d_in[0];
    const float* cosp = (const float*)d_in[1];
    const float* sinp = (const float*)d_in[2];
    const float* Wq   = (const float*)d_in[3];
    const float* bq   = (const float*)d_in[4];
    const float* Wk   = (const float*)d_in[5];
    const float* bk   = (const float*)d_in[6];
    const float* Wv   = (const float*)d_in[7];
    const float* bv   = (const float*)d_in[8];
    const float* Wo   = (const float*)d_in[9];
    float* out = (float*)d_out;

    void *phs, *pwqkv, *pwo, *pctx, *pqkv, *pb;
    cudaGetSymbolAddress(&phs, g_hs_h);
    cudaGetSymbolAddress(&pwqkv, g_wqkv_h);
    cudaGetSymbolAddress(&pwo, g_wo_h);
    cudaGetSymbolAddress(&pctx, g_ctx_h);
    cudaGetSymbolAddress(&pqkv, g_qkv_h);
    cudaGetSymbolAddress(&pb, g_bias);

    cudaFuncSetAttribute(gemm_h, cudaFuncAttributeMaxDynamicSharedMemorySize, SMEM_BYTES);

    // one fused conversion / packing pass
    conv_all<<<2048, 256>>>((const float4*)hs,
                            (const float4*)Wq, (const float4*)Wk, (const float4*)Wv,
                            (const float4*)Wo, bq, bk, bv,
                            (uint2*)phs, (uint2*)pwqkv, (uint2*)pwo, (float*)pb);

    // fused QKV projection: [M,2048] @ [2048,3072] -> fp16
    gemm_h<<<dim3(NQKV / BN, M_ROWS / BM), 256, SMEM_BYTES>>>(
        (const __half*)phs, (const __half*)pwqkv, (const float*)pb, pqkv, NQKV, 1);

    // replica attention (fp16 in, fp16 ctx out)
    attn_kernel<<<dim3(2048, 2), 128>>>((const __half*)pqkv, cosp, sinp, (__half*)pctx);

    // output projection -> fp32
    gemm_h<<<dim3(2048 / BN, M_ROWS / BM), 256, SMEM_BYTES>>>(
        (const __half*)pctx, (const __half*)pwo, nullptr, out, 2048, 0);
}